// round 1
// baseline (speedup 1.0000x reference)
#include <cuda_runtime.h>
#include <cuda_bf16.h>
#include <math.h>

#define NUM_ITEMS 10000
#define EMBED 64
#define BATCH 32
#define MAX_HIST 200
#define LEAKY 0.2f

// Scratch (allocation-free rule: __device__ globals)
__device__ float g_G[NUM_ITEMS * EMBED];        // E @ W          (2.56 MB)
__device__ float g_c[NUM_ITEMS];                // E[i] . bias
__device__ float g_hist[BATCH * MAX_HIST * EMBED]; // gathered hist (1.64 MB)
__device__ float g_hbar[BATCH * EMBED];         // user-softmax-weighted hist sum

// ---------------------------------------------------------------------------
// Kernel 1: G[i,:] = E[i,:] @ W ; c[i] = E[i,:] . bias
// one block (64 threads) per item
// ---------------------------------------------------------------------------
__global__ void gproj_kernel(const float* __restrict__ E,
                             const float* __restrict__ W,
                             const float* __restrict__ bias) {
    __shared__ float s_e[EMBED];
    __shared__ float s_c[2];
    int i = blockIdx.x;
    int g = threadIdx.x;              // 0..63
    s_e[g] = E[i * EMBED + g];
    __syncthreads();
    float acc = 0.f;
#pragma unroll 16
    for (int f = 0; f < EMBED; f++)
        acc = fmaf(s_e[f], W[f * EMBED + g], acc);
    g_G[i * EMBED + g] = acc;

    float p = s_e[g] * bias[g];
#pragma unroll
    for (int off = 16; off; off >>= 1)
        p += __shfl_xor_sync(0xffffffffu, p, off);
    if ((g & 31) == 0) s_c[g >> 5] = p;
    __syncthreads();
    if (g == 0) g_c[i] = s_c[0] + s_c[1];
}

// ---------------------------------------------------------------------------
// Kernel 2: per batch b — gather hist rows, user-perspective softmax, hbar
// one block (256 threads) per batch
// ---------------------------------------------------------------------------
__global__ void prep_kernel(const int* __restrict__ ids,
                            const int* __restrict__ lens,
                            const float* __restrict__ E,
                            const float* __restrict__ U) {
    __shared__ float s_u[EMBED];
    __shared__ float s_p[256];
    __shared__ float s_red[256];
    int b = blockIdx.x;
    int tid = threadIdx.x;
    int len = lens[b];

    if (tid < EMBED) s_u[tid] = U[tid];

    // gather hist[b] into global scratch (coalesced per warp)
    float* hb = g_hist + b * MAX_HIST * EMBED;
    for (int k = tid; k < MAX_HIST * EMBED; k += 256) {
        int n = k >> 6;
        int f = k & 63;
        hb[k] = E[ids[b * MAX_HIST + n] * EMBED + f];
    }
    __syncthreads();   // orders global writes for block-local reads

    // user logits (leaky) for valid n
    float la = -1e30f;
    if (tid < len) {
        const float* h = hb + tid * EMBED;
        float a = 0.f;
#pragma unroll 16
        for (int f = 0; f < EMBED; f++) a = fmaf(s_u[f], h[f], a);
        la = (a > 0.f) ? a : LEAKY * a;
    }
    // block max
    s_red[tid] = la;
    __syncthreads();
#pragma unroll
    for (int off = 128; off; off >>= 1) {
        if (tid < off) s_red[tid] = fmaxf(s_red[tid], s_red[tid + off]);
        __syncthreads();
    }
    float m = s_red[0];
    __syncthreads();
    // block sum of exp
    float ev = (tid < len) ? __expf(la - m) : 0.f;
    s_red[tid] = ev;
    __syncthreads();
#pragma unroll
    for (int off = 128; off; off >>= 1) {
        if (tid < off) s_red[tid] += s_red[tid + off];
        __syncthreads();
    }
    float Z = s_red[0];
    s_p[tid] = ev / Z;
    __syncthreads();

    // hbar[f] = sum_n p[n] * hist[n][f]
    if (tid < EMBED) {
        float acc = 0.f;
        for (int n = 0; n < len; n++)
            acc = fmaf(s_p[n], hb[n * EMBED + tid], acc);
        g_hbar[b * EMBED + tid] = acc;
    }
}

// ---------------------------------------------------------------------------
// Kernel 3 (main): per (batch, item-tile). Thread-per-item, hist in smem,
// online softmax over valid n with scalar score accumulator.
// out[b,i] = 0.5*acc/Z + 0.5*(G[i].hbar[b]) + c[i]
// ---------------------------------------------------------------------------
__global__ __launch_bounds__(256)
void main_kernel(const float* __restrict__ E,
                 const int* __restrict__ lens,
                 float* __restrict__ out) {
    extern __shared__ float smem[];
    float* sh_hist = smem;                       // MAX_HIST*EMBED
    float* sh_hbar = smem + MAX_HIST * EMBED;    // EMBED

    int b = blockIdx.y;
    int tid = threadIdx.x;
    int len = lens[b];

    // stage hist[b] into smem (contiguous float4 copy)
    {
        const float4* src = (const float4*)(g_hist + b * MAX_HIST * EMBED);
        float4* dst = (float4*)sh_hist;
        for (int k = tid; k < MAX_HIST * EMBED / 4; k += 256) dst[k] = src[k];
        if (tid < EMBED) sh_hbar[tid] = g_hbar[b * EMBED + tid];
    }
    __syncthreads();

    int i = blockIdx.x * 256 + tid;
    if (i >= NUM_ITEMS) return;

    // register-resident E and G rows (32 float4 = 128 regs)
    float4 e[16], g[16];
    {
        const float4* ep = (const float4*)(E + i * EMBED);
        const float4* gp = (const float4*)(g_G + i * EMBED);
#pragma unroll
        for (int k = 0; k < 16; k++) { e[k] = ep[k]; g[k] = gp[k]; }
    }

    const float4* h4 = (const float4*)sh_hist;
    float m = -1e30f, Z = 0.f, acc = 0.f;

    for (int n = 0; n < len; n++) {
        const float4* hh = h4 + n * 16;
        float a0 = 0.f, a1 = 0.f, s0 = 0.f, s1 = 0.f;
#pragma unroll
        for (int k = 0; k < 16; k += 2) {
            float4 h0 = hh[k];
            float4 h1 = hh[k + 1];
            a0 = fmaf(e[k].x, h0.x, a0); a0 = fmaf(e[k].y, h0.y, a0);
            a0 = fmaf(e[k].z, h0.z, a0); a0 = fmaf(e[k].w, h0.w, a0);
            s0 = fmaf(g[k].x, h0.x, s0); s0 = fmaf(g[k].y, h0.y, s0);
            s0 = fmaf(g[k].z, h0.z, s0); s0 = fmaf(g[k].w, h0.w, s0);
            a1 = fmaf(e[k+1].x, h1.x, a1); a1 = fmaf(e[k+1].y, h1.y, a1);
            a1 = fmaf(e[k+1].z, h1.z, a1); a1 = fmaf(e[k+1].w, h1.w, a1);
            s1 = fmaf(g[k+1].x, h1.x, s1); s1 = fmaf(g[k+1].y, h1.y, s1);
            s1 = fmaf(g[k+1].z, h1.z, s1); s1 = fmaf(g[k+1].w, h1.w, s1);
        }
        float a = a0 + a1;
        float s = s0 + s1;
        float l = (a > 0.f) ? a : LEAKY * a;
        float nm = fmaxf(m, l);
        float corr = __expf(m - nm);   // 0 on first iter (m = -1e30)
        float t = __expf(l - nm);
        Z = fmaf(Z, corr, t);
        acc = fmaf(acc, corr, t * s);
        m = nm;
    }

    // user half: G[i] . hbar
    float u0 = 0.f, u1 = 0.f;
#pragma unroll
    for (int k = 0; k < 16; k += 2) {
        float4 h0 = ((const float4*)sh_hbar)[k];
        float4 h1 = ((const float4*)sh_hbar)[k + 1];
        u0 = fmaf(g[k].x, h0.x, u0); u0 = fmaf(g[k].y, h0.y, u0);
        u0 = fmaf(g[k].z, h0.z, u0); u0 = fmaf(g[k].w, h0.w, u0);
        u1 = fmaf(g[k+1].x, h1.x, u1); u1 = fmaf(g[k+1].y, h1.y, u1);
        u1 = fmaf(g[k+1].z, h1.z, u1); u1 = fmaf(g[k+1].w, h1.w, u1);
    }
    float ub = u0 + u1;

    out[b * NUM_ITEMS + i] = 0.5f * (acc / Z) + 0.5f * ub + g_c[i];
}

// ---------------------------------------------------------------------------
extern "C" void kernel_launch(void* const* d_in, const int* in_sizes, int n_in,
                              void* d_out, int out_size) {
    const int*   ids  = (const int*)d_in[0];    // [32,200] int32
    const int*   lens = (const int*)d_in[1];    // [32] int32
    const float* E    = (const float*)d_in[2];  // [10000,64]
    const float* U    = (const float*)d_in[3];  // [1,64]
    const float* W    = (const float*)d_in[4];  // [64,64]
    const float* bias = (const float*)d_in[5];  // [64]
    float* out = (float*)d_out;                 // [32,10000]

    gproj_kernel<<<NUM_ITEMS, EMBED>>>(E, W, bias);
    prep_kernel<<<BATCH, 256>>>(ids, lens, E, U);

    size_t smem = (MAX_HIST * EMBED + EMBED) * sizeof(float);  // 51456 B
    cudaFuncSetAttribute(main_kernel,
                         cudaFuncAttributeMaxDynamicSharedMemorySize, (int)smem);
    dim3 grid((NUM_ITEMS + 255) / 256, BATCH);
    main_kernel<<<grid, 256, smem>>>(E, lens, out);
}

// round 2
// speedup vs baseline: 1.2884x; 1.2884x over previous
#include <cuda_runtime.h>
#include <cuda_bf16.h>
#include <math.h>

#define NUM_ITEMS 10000
#define EMBED 64
#define BATCH 32
#define MAX_HIST 200
#define LEAKY 0.2f

typedef unsigned long long u64;

// Scratch (allocation-free rule: __device__ globals)
__device__ float g_G[NUM_ITEMS * EMBED];           // E @ W
__device__ float g_c[NUM_ITEMS];                   // E[i] . bias
__device__ float g_hist[BATCH * MAX_HIST * EMBED]; // gathered hist
__device__ float g_hbar[BATCH * EMBED];            // user-weighted hist sum

// packed f32x2 FMA: d = a*b + d  (elementwise on 2 packed floats)
__device__ __forceinline__ void ffma2(u64& d, u64 a, u64 b) {
    asm("fma.rn.f32x2 %0, %1, %2, %0;" : "+l"(d) : "l"(a), "l"(b));
}
__device__ __forceinline__ float hsum2(u64 v) {
    unsigned lo, hi;
    asm("mov.b64 {%0,%1}, %2;" : "=r"(lo), "=r"(hi) : "l"(v));
    return __uint_as_float(lo) + __uint_as_float(hi);
}

// ---------------------------------------------------------------------------
// Kernel 1: G[i,:] = E[i,:] @ W ; c[i] = E[i,:] . bias     (1 block / item)
// ---------------------------------------------------------------------------
__global__ void gproj_kernel(const float* __restrict__ E,
                             const float* __restrict__ W,
                             const float* __restrict__ bias) {
    __shared__ float s_e[EMBED];
    __shared__ float s_c[2];
    int i = blockIdx.x;
    int g = threadIdx.x;  // 0..63
    s_e[g] = E[i * EMBED + g];
    __syncthreads();
    float acc = 0.f;
#pragma unroll 16
    for (int f = 0; f < EMBED; f++)
        acc = fmaf(s_e[f], W[f * EMBED + g], acc);
    g_G[i * EMBED + g] = acc;

    float p = s_e[g] * bias[g];
#pragma unroll
    for (int off = 16; off; off >>= 1)
        p += __shfl_xor_sync(0xffffffffu, p, off);
    if ((g & 31) == 0) s_c[g >> 5] = p;
    __syncthreads();
    if (g == 0) g_c[i] = s_c[0] + s_c[1];
}

// ---------------------------------------------------------------------------
// Kernel 2: per batch — gather hist, user softmax, hbar    (1 block / batch)
// ---------------------------------------------------------------------------
__global__ void prep_kernel(const int* __restrict__ ids,
                            const int* __restrict__ lens,
                            const float* __restrict__ E,
                            const float* __restrict__ U) {
    __shared__ float s_u[EMBED];
    __shared__ float s_p[256];
    __shared__ float s_red[256];
    int b = blockIdx.x;
    int tid = threadIdx.x;
    int len = lens[b];

    if (tid < EMBED) s_u[tid] = U[tid];

    float* hb = g_hist + b * MAX_HIST * EMBED;
    for (int k = tid; k < MAX_HIST * EMBED; k += 256) {
        int n = k >> 6;
        int f = k & 63;
        hb[k] = E[ids[b * MAX_HIST + n] * EMBED + f];
    }
    __syncthreads();

    float la = -1e30f;
    if (tid < len) {
        const float* h = hb + tid * EMBED;
        float a = 0.f;
#pragma unroll 16
        for (int f = 0; f < EMBED; f++) a = fmaf(s_u[f], h[f], a);
        la = (a > 0.f) ? a : LEAKY * a;
    }
    s_red[tid] = la;
    __syncthreads();
#pragma unroll
    for (int off = 128; off; off >>= 1) {
        if (tid < off) s_red[tid] = fmaxf(s_red[tid], s_red[tid + off]);
        __syncthreads();
    }
    float m = s_red[0];
    __syncthreads();
    float ev = (tid < len) ? __expf(la - m) : 0.f;
    s_red[tid] = ev;
    __syncthreads();
#pragma unroll
    for (int off = 128; off; off >>= 1) {
        if (tid < off) s_red[tid] += s_red[tid + off];
        __syncthreads();
    }
    float Z = s_red[0];
    s_p[tid] = ev / Z;
    __syncthreads();

    if (tid < EMBED) {
        float acc = 0.f;
        for (int n = 0; n < len; n++)
            acc = fmaf(s_p[n], hb[n * EMBED + tid], acc);
        g_hbar[b * EMBED + tid] = acc;
    }
}

// ---------------------------------------------------------------------------
// Kernel 3 (main): thread-per-item, hist in smem, online softmax with
// scalar score accumulator; dual 64-dots via packed fma.rn.f32x2.
// out[b,i] = 0.5*acc/Z + 0.5*(G[i].hbar[b]) + c[i]
// ---------------------------------------------------------------------------
__global__ __launch_bounds__(256)
void main_kernel(const float* __restrict__ E,
                 const int* __restrict__ lens,
                 float* __restrict__ out) {
    extern __shared__ float smem[];
    float* sh_hist = smem;                    // MAX_HIST*EMBED
    float* sh_hbar = smem + MAX_HIST * EMBED; // EMBED

    int b = blockIdx.y;
    int tid = threadIdx.x;
    int len = lens[b];

    {
        const float4* src = (const float4*)(g_hist + b * MAX_HIST * EMBED);
        float4* dst = (float4*)sh_hist;
        for (int k = tid; k < MAX_HIST * EMBED / 4; k += 256) dst[k] = src[k];
        if (tid < EMBED) sh_hbar[tid] = g_hbar[b * EMBED + tid];
    }
    __syncthreads();

    int i = blockIdx.x * 256 + tid;
    if (i >= NUM_ITEMS) return;

    // E and G rows, register-resident as packed f32x2 (32 u64 each)
    u64 e2[32], g2[32];
    {
        const ulonglong2* ep = (const ulonglong2*)(E + i * EMBED);
        const ulonglong2* gp = (const ulonglong2*)(g_G + i * EMBED);
#pragma unroll
        for (int k = 0; k < 16; k++) {
            ulonglong2 ev = ep[k]; e2[2*k] = ev.x; e2[2*k+1] = ev.y;
            ulonglong2 gv = gp[k]; g2[2*k] = gv.x; g2[2*k+1] = gv.y;
        }
    }

    const ulonglong2* h2 = (const ulonglong2*)sh_hist;  // 16 u64x2 per row
    float m = -1e30f, Z = 0.f, acc = 0.f;

    for (int n = 0; n < len; n++) {
        const ulonglong2* hh = h2 + n * 16;
        u64 a0 = 0, a1 = 0, s0 = 0, s1 = 0;   // packed accumulators
#pragma unroll
        for (int k = 0; k < 16; k += 2) {
            ulonglong2 hA = hh[k];       // LDS.128: 2 packed f32x2
            ulonglong2 hB = hh[k + 1];
            ffma2(a0, e2[2*k],     hA.x);
            ffma2(s0, g2[2*k],     hA.x);
            ffma2(a1, e2[2*k+1],   hA.y);
            ffma2(s1, g2[2*k+1],   hA.y);
            ffma2(a0, e2[2*k+2],   hB.x);
            ffma2(s0, g2[2*k+2],   hB.x);
            ffma2(a1, e2[2*k+3],   hB.y);
            ffma2(s1, g2[2*k+3],   hB.y);
        }
        float a = hsum2(a0) + hsum2(a1);
        float s = hsum2(s0) + hsum2(s1);
        float l = (a > 0.f) ? a : LEAKY * a;
        float nm = fmaxf(m, l);
        float corr = __expf(m - nm);  // 0 on first iter
        float t = __expf(l - nm);
        Z = fmaf(Z, corr, t);
        acc = fmaf(acc, corr, t * s);
        m = nm;
    }

    // user half: G[i] . hbar (packed)
    u64 u0 = 0, u1 = 0;
    {
        const ulonglong2* hb = (const ulonglong2*)sh_hbar;
#pragma unroll
        for (int k = 0; k < 16; k++) {
            ulonglong2 hv = hb[k];
            ffma2(u0, g2[2*k],   hv.x);
            ffma2(u1, g2[2*k+1], hv.y);
        }
    }
    float ub = hsum2(u0) + hsum2(u1);

    out[b * NUM_ITEMS + i] = 0.5f * (acc / Z) + 0.5f * ub + g_c[i];
}

// ---------------------------------------------------------------------------
extern "C" void kernel_launch(void* const* d_in, const int* in_sizes, int n_in,
                              void* d_out, int out_size) {
    const int*   ids  = (const int*)d_in[0];    // [32,200] int32
    const int*   lens = (const int*)d_in[1];    // [32] int32
    const float* E    = (const float*)d_in[2];  // [10000,64]
    const float* U    = (const float*)d_in[3];  // [1,64]
    const float* W    = (const float*)d_in[4];  // [64,64]
    const float* bias = (const float*)d_in[5];  // [64]
    float* out = (float*)d_out;                 // [32,10000]

    gproj_kernel<<<NUM_ITEMS, EMBED>>>(E, W, bias);
    prep_kernel<<<BATCH, 256>>>(ids, lens, E, U);

    size_t smem = (MAX_HIST * EMBED + EMBED) * sizeof(float);  // 51456 B
    cudaFuncSetAttribute(main_kernel,
                         cudaFuncAttributeMaxDynamicSharedMemorySize, (int)smem);
    dim3 grid((NUM_ITEMS + 255) / 256, BATCH);
    main_kernel<<<grid, 256, smem>>>(E, lens, out);
}